// round 6
// baseline (speedup 1.0000x reference)
#include <cuda_runtime.h>
#include <cstdint>

// ---------------- problem shapes (fixed by the dataset) ----------------
constexpr int B    = 8;
constexpr int C    = 19;
constexpr int H    = 512;
constexpr int W    = 1024;
constexpr int HW   = H * W;            // 524288 = 2^19
constexpr int NPIX = B * HW;           // 4194304
constexpr int Hh   = 128;
constexpr int Wh   = 256;
constexpr int HhWh = Hh * Wh;          // 32768
constexpr int NHEAT = B * HhWh;        // 262144
constexpr int NBOX  = 8 * 64;          // 512

constexpr float OHEM_THRESH = 0.22314355513142097f;  // -log(0.8)
constexpr int   NBINS = 4096;
constexpr float BIN_SCALE = (float)NBINS / OHEM_THRESH;
constexpr float F32_TINY = 1.17549435e-38f;
constexpr float L2E  = 1.4426950408889634f;   // log2(e)
constexpr float LN2  = 0.6931471805599453f;   // ln(2)

constexpr int THREADS      = 256;
constexpr int QUADS        = NPIX / 4;                    // 1048576
constexpr int OHEM_BLOCKS  = QUADS / THREADS;             // 4096
constexpr int FOCAL_BLOCKS = NHEAT / (THREADS * 4);       // 256
constexpr int TOTAL_BLOCKS = OHEM_BLOCKS + FOCAL_BLOCKS + 1;  // 4353

// ---------------- device accumulators (zero at load; final block re-zeros
// them each run so graph replays stay deterministic) ----------------
__device__ double             g_sum_hard;
__device__ unsigned long long g_cnt_hard;
__device__ unsigned long long g_cnt_valid;
__device__ double             g_hist_sum[NBINS];
__device__ unsigned int       g_hist_cnt[NBINS];
__device__ double             g_pos_loss;
__device__ double             g_neg_loss;
__device__ double             g_npos;
__device__ double             g_reg_sum;
__device__ unsigned int       g_done;

__device__ __forceinline__ float ex2f(float x) {
    float r;
    asm("ex2.approx.ftz.f32 %0, %1;" : "=f"(r) : "f"(x));
    return r;
}
__device__ __forceinline__ float lg2f(float x) {
    float r;
    asm("lg2.approx.ftz.f32 %0, %1;" : "=f"(r) : "f"(x));
    return r;
}

// ---------------- one fused kernel ----------------
__global__ __launch_bounds__(THREADS, 6) void fused_loss_kernel(
    const float* __restrict__ seg,     const int*   __restrict__ masks,
    const float* __restrict__ hm_pred, const float* __restrict__ hm_tgt,
    const float* __restrict__ wh,      const float* __restrict__ bboxes,
    const int*   __restrict__ ct,      float* __restrict__ out)
{
    const int bid  = blockIdx.x;
    const int tid  = threadIdx.x;
    const int lane = tid & 31, wid = tid >> 5;

    __shared__ float    s_f0[8], s_f1[8], s_f2[8];
    __shared__ unsigned s_u0[8], s_u1[8];

    if (bid < OHEM_BLOCKS) {
        // ====== OHEM CE: 4 pixels/thread, streaming softmax (no max, no array) ======
        int q  = bid * THREADS + tid;            // quad index
        int b  = q >> 17;                        // / (HW/4)
        int hq = q & (HW / 4 - 1);               // quad offset within image
        const float* img = seg + (size_t)b * C * HW;
        const float4* base4 = (const float4*)img + hq;

        int4 tt = __ldg((const int4*)masks + q);
        bool valid0 = (tt.x != 255), valid1 = (tt.y != 255);
        bool valid2 = (tt.z != 255), valid3 = (tt.w != 255);
        int t0 = valid0 ? tt.x : 0;
        int t1 = valid1 ? tt.y : 0;
        int t2 = valid2 ? tt.z : 0;
        int t3 = valid3 ? tt.w : 0;

        float s0 = 0.0f, s1 = 0.0f, s2 = 0.0f, s3 = 0.0f;
        #pragma unroll
        for (int c = 0; c < C; c++) {
            float4 v = __ldg(base4 + (size_t)c * (HW / 4));
            s0 += ex2f(v.x * L2E);
            s1 += ex2f(v.y * L2E);
            s2 += ex2f(v.z * L2E);
            s3 += ex2f(v.w * L2E);
        }

        // target logits via direct (cache-hit) gathers
        int hw0 = hq * 4;
        float xt0 = __ldg(img + (size_t)t0 * HW + hw0 + 0);
        float xt1 = __ldg(img + (size_t)t1 * HW + hw0 + 1);
        float xt2 = __ldg(img + (size_t)t2 * HW + hw0 + 2);
        float xt3 = __ldg(img + (size_t)t3 * HW + hw0 + 3);

        float ce0 = valid0 ? __fmaf_rn(lg2f(s0), LN2, -xt0) : 0.0f;
        float ce1 = valid1 ? __fmaf_rn(lg2f(s1), LN2, -xt1) : 0.0f;
        float ce2 = valid2 ? __fmaf_rn(lg2f(s2), LN2, -xt2) : 0.0f;
        float ce3 = valid3 ? __fmaf_rn(lg2f(s3), LN2, -xt3) : 0.0f;

        bool h0 = ce0 > OHEM_THRESH, h1 = ce1 > OHEM_THRESH;
        bool h2 = ce2 > OHEM_THRESH, h3 = ce3 > OHEM_THRESH;

        // rare path: ce <= THRESH -> global histogram (expected ~handful of hits)
        if (!(h0 && h1 && h2 && h3)) {
            float ces[4] = {ce0, ce1, ce2, ce3};
            bool  hs[4]  = {h0, h1, h2, h3};
            #pragma unroll
            for (int k = 0; k < 4; k++) {
                if (!hs[k]) {
                    int bin = min(max((int)(ces[k] * BIN_SCALE), 0), NBINS - 1);
                    atomicAdd(&g_hist_cnt[bin], 1u);
                    atomicAdd(&g_hist_sum[bin], (double)ces[k]);
                }
            }
        }

        float    fs = (h0 ? ce0 : 0.0f) + (h1 ? ce1 : 0.0f)
                    + (h2 ? ce2 : 0.0f) + (h3 ? ce3 : 0.0f);
        unsigned hc = (unsigned)h0 + (unsigned)h1 + (unsigned)h2 + (unsigned)h3;
        unsigned vc = (unsigned)valid0 + (unsigned)valid1
                    + (unsigned)valid2 + (unsigned)valid3;
        #pragma unroll
        for (int o = 16; o > 0; o >>= 1) {
            fs += __shfl_xor_sync(0xffffffffu, fs, o);
            hc += __shfl_xor_sync(0xffffffffu, hc, o);
            vc += __shfl_xor_sync(0xffffffffu, vc, o);
        }
        if (lane == 0) { s_f0[wid] = fs; s_u0[wid] = hc; s_u1[wid] = vc; }
        __syncthreads();
        if (tid == 0) {
            double ts = 0.0; unsigned th = 0, tv = 0;
            #pragma unroll
            for (int i = 0; i < 8; i++) { ts += (double)s_f0[i]; th += s_u0[i]; tv += s_u1[i]; }
            atomicAdd(&g_sum_hard, ts);
            atomicAdd(&g_cnt_hard, (unsigned long long)th);
            atomicAdd(&g_cnt_valid, (unsigned long long)tv);
        }
    } else if (bid < OHEM_BLOCKS + FOCAL_BLOCKS) {
        // ============ focal: 4 elems per thread via float4 ============
        int i4 = (bid - OHEM_BLOCKS) * THREADS + tid;
        float4 pv  = __ldg((const float4*)hm_pred + i4);
        float4 tv4 = __ldg((const float4*)hm_tgt + i4);

        float pl = 0.0f, nl = 0.0f, np = 0.0f;
        const float* pp = &pv.x;
        const float* tp = &tv4.x;
        #pragma unroll
        for (int k = 0; k < 4; k++) {
            float p = fmaxf(pp[k], F32_TINY);
            float t = tp[k];
            if (t == 1.0f) {
                float om = 1.0f - p;
                pl += lg2f(p) * LN2 * om * om;
                np += 1.0f;
            } else {
                float omt = 1.0f - t;
                float wgt = omt * omt; wgt *= wgt;
                nl += lg2f(1.0f - p + F32_TINY) * LN2 * p * p * wgt;
            }
        }
        #pragma unroll
        for (int o = 16; o > 0; o >>= 1) {
            pl += __shfl_xor_sync(0xffffffffu, pl, o);
            nl += __shfl_xor_sync(0xffffffffu, nl, o);
            np += __shfl_xor_sync(0xffffffffu, np, o);
        }
        if (lane == 0) { s_f0[wid] = pl; s_f1[wid] = nl; s_f2[wid] = np; }
        __syncthreads();
        if (tid == 0) {
            double tpd = 0, tnd = 0, tcd = 0;
            #pragma unroll
            for (int k = 0; k < 8; k++) { tpd += (double)s_f0[k]; tnd += (double)s_f1[k]; tcd += (double)s_f2[k]; }
            atomicAdd(&g_pos_loss, tpd);
            atomicAdd(&g_neg_loss, tnd);
            atomicAdd(&g_npos, tcd);
        }
    } else {
        // ============ L1 regression (512 boxes, 2 per thread) ============
        float l1 = 0.0f;
        #pragma unroll
        for (int r = 0; r < 2; r++) {
            int i = tid + r * THREADS;
            int b = i >> 6;
            int x = ct[i * 2 + 0];
            int y = ct[i * 2 + 1];
            const float* whb = wh + (size_t)b * 2 * HhWh;
            float v0 = whb[y * Wh + x];
            float v1 = whb[HhWh + y * Wh + x];
            const float* bb = bboxes + (size_t)i * 4;
            float w = bb[2] - bb[0];
            float h = bb[3] - bb[1];
            l1 += fabsf(v0 - w) + fabsf(v1 - h);
        }
        #pragma unroll
        for (int o = 16; o > 0; o >>= 1) l1 += __shfl_xor_sync(0xffffffffu, l1, o);
        if (lane == 0) s_f0[wid] = l1;
        __syncthreads();
        if (tid == 0) {
            double tot = 0.0;
            #pragma unroll
            for (int k = 0; k < 8; k++) tot += (double)s_f0[k];
            g_reg_sum = tot;
        }
    }

    // ===================== last-block election =====================
    __shared__ bool s_last;
    __syncthreads();
    if (tid == 0) {
        __threadfence();
        unsigned prev = atomicAdd(&g_done, 1u);
        s_last = (prev == (unsigned)(TOTAL_BLOCKS - 1));
    }
    __syncthreads();
    if (!s_last) return;
    __threadfence();

    __shared__ float s_out[4];
    if (tid == 0) {
        // classification (OHEM)
        unsigned long long nmin = g_cnt_valid / 16ull;
        double k, top;
        if (g_cnt_hard >= nmin) {
            k = (double)g_cnt_hard;
            top = g_sum_hard;
        } else {
            k = (double)nmin;
            top = g_sum_hard;
            double need = (double)(nmin - g_cnt_hard);
            for (int bin = NBINS - 1; bin >= 0 && need > 0.0; --bin) {
                unsigned c = g_hist_cnt[bin];
                if (!c) continue;
                if ((double)c <= need) { top += g_hist_sum[bin]; need -= (double)c; }
                else                   { top += g_hist_sum[bin] * (need / (double)c); need = 0.0; }
            }
        }
        float cls = (k > 0.0) ? (float)(top / k) : 0.0f;

        // centerness (focal)
        double npos = g_npos;
        double fl = (npos == 0.0) ? -g_neg_loss
                                  : -(g_pos_loss + g_neg_loss) / fmax(npos, 1.0);
        float centerness = (float)fl;

        // bbox
        float regression = (float)g_reg_sum * 0.7f;
        float bbox = regression / ((float)NBOX + 1e-7f) * 0.1f;
        float localization = (centerness + bbox) * 1.0f;

        s_out[0] = cls;
        s_out[1] = localization;
        s_out[2] = centerness;
        s_out[3] = bbox;
    }
    __syncthreads();

    if (tid < 4) out[tid] = s_out[tid];
    for (int bin = tid; bin < NBINS; bin += THREADS) {
        g_hist_sum[bin] = 0.0;
        g_hist_cnt[bin] = 0u;
    }
    if (tid == 0) {
        g_sum_hard = 0.0; g_cnt_hard = 0ull; g_cnt_valid = 0ull;
        g_pos_loss = 0.0; g_neg_loss = 0.0; g_npos = 0.0; g_reg_sum = 0.0;
        __threadfence();
        g_done = 0u;
    }
}

// ---------------- launch ----------------
extern "C" void kernel_launch(void* const* d_in, const int* in_sizes, int n_in,
                              void* d_out, int out_size)
{
    const float* seg     = (const float*)d_in[0];
    const int*   masks   = (const int*)  d_in[1];
    const float* hm_pred = (const float*)d_in[2];
    const float* hm_tgt  = (const float*)d_in[3];
    const float* wh      = (const float*)d_in[4];
    const float* bboxes  = (const float*)d_in[5];
    // d_in[6] = labels (unused by the reference loss)
    const int*   ct      = (const int*)  d_in[7];
    float* out = (float*)d_out;

    fused_loss_kernel<<<TOTAL_BLOCKS, THREADS>>>(
        seg, masks, hm_pred, hm_tgt, wh, bboxes, ct, out);
}

// round 7
// speedup vs baseline: 1.0875x; 1.0875x over previous
#include <cuda_runtime.h>
#include <cstdint>

// ---------------- problem shapes (fixed by the dataset) ----------------
constexpr int B    = 8;
constexpr int C    = 19;
constexpr int H    = 512;
constexpr int W    = 1024;
constexpr int HW   = H * W;            // 524288 = 2^19
constexpr int NPIX = B * HW;           // 4194304
constexpr int Hh   = 128;
constexpr int Wh   = 256;
constexpr int HhWh = Hh * Wh;          // 32768
constexpr int NHEAT = B * HhWh;        // 262144
constexpr int NBOX  = 8 * 64;          // 512

constexpr float OHEM_THRESH = 0.22314355513142097f;  // -log(0.8)
constexpr int   NBINS = 4096;
constexpr float BIN_SCALE = (float)NBINS / OHEM_THRESH;
constexpr float F32_TINY = 1.17549435e-38f;
constexpr float L2E  = 1.4426950408889634f;   // log2(e)
constexpr float LN2  = 0.6931471805599453f;   // ln(2)

constexpr int THREADS      = 256;
constexpr int QUADS        = NPIX / 4;                    // 1048576
constexpr int OHEM_BLOCKS  = QUADS / THREADS;             // 4096
constexpr int FOCAL_BLOCKS = NHEAT / (THREADS * 4);       // 256
constexpr int TOTAL_BLOCKS = OHEM_BLOCKS + FOCAL_BLOCKS + 1;  // 4353

// ---------------- device accumulators (zero at load; final block re-zeros
// them each run so graph replays stay deterministic) ----------------
__device__ double             g_sum_hard;
__device__ unsigned long long g_cnt_hard;
__device__ unsigned long long g_cnt_valid;
__device__ double             g_hist_sum[NBINS];
__device__ unsigned int       g_hist_cnt[NBINS];
__device__ double             g_pos_loss;
__device__ double             g_neg_loss;
__device__ double             g_npos;
__device__ double             g_reg_sum;
__device__ unsigned int       g_done;

__device__ __forceinline__ float ex2f(float x) {
    float r;
    asm("ex2.approx.ftz.f32 %0, %1;" : "=f"(r) : "f"(x));
    return r;
}
__device__ __forceinline__ float lg2f(float x) {
    float r;
    asm("lg2.approx.ftz.f32 %0, %1;" : "=f"(r) : "f"(x));
    return r;
}

// ---------------- one fused kernel ----------------
__global__ __launch_bounds__(THREADS, 6) void fused_loss_kernel(
    const float* __restrict__ seg,     const int*   __restrict__ masks,
    const float* __restrict__ hm_pred, const float* __restrict__ hm_tgt,
    const float* __restrict__ wh,      const float* __restrict__ bboxes,
    const int*   __restrict__ ct,      float* __restrict__ out)
{
    const int bid  = blockIdx.x;
    const int tid  = threadIdx.x;
    const int lane = tid & 31, wid = tid >> 5;

    __shared__ float    s_f0[8], s_f1[8], s_f2[8];
    __shared__ unsigned s_u0[8], s_u1[8];

    if (bid < OHEM_BLOCKS) {
        // === OHEM CE: 4 pixels/thread, streaming softmax, in-loop target select ===
        int q  = bid * THREADS + tid;            // quad index
        int b  = q >> 17;                        // / (HW/4)
        int hq = q & (HW / 4 - 1);               // quad offset within image
        const float* img = seg + (size_t)b * C * HW;
        const float4* base4 = (const float4*)img + hq;

        int4 tt = __ldcs((const int4*)masks + q);
        bool valid0 = (tt.x != 255), valid1 = (tt.y != 255);
        bool valid2 = (tt.z != 255), valid3 = (tt.w != 255);
        int t0 = tt.x, t1 = tt.y, t2 = tt.z, t3 = tt.w;

        float s0 = 0.0f, s1 = 0.0f, s2 = 0.0f, s3 = 0.0f;
        float xt0 = 0.0f, xt1 = 0.0f, xt2 = 0.0f, xt3 = 0.0f;
        #pragma unroll
        for (int c = 0; c < C; c++) {
            float4 v = __ldcs(base4 + (size_t)c * (HW / 4));
            s0 += ex2f(v.x * L2E);
            s1 += ex2f(v.y * L2E);
            s2 += ex2f(v.z * L2E);
            s3 += ex2f(v.w * L2E);
            xt0 = (c == t0) ? v.x : xt0;
            xt1 = (c == t1) ? v.y : xt1;
            xt2 = (c == t2) ? v.z : xt2;
            xt3 = (c == t3) ? v.w : xt3;
        }

        float ce0 = valid0 ? __fmaf_rn(lg2f(s0), LN2, -xt0) : 0.0f;
        float ce1 = valid1 ? __fmaf_rn(lg2f(s1), LN2, -xt1) : 0.0f;
        float ce2 = valid2 ? __fmaf_rn(lg2f(s2), LN2, -xt2) : 0.0f;
        float ce3 = valid3 ? __fmaf_rn(lg2f(s3), LN2, -xt3) : 0.0f;

        bool h0 = ce0 > OHEM_THRESH, h1 = ce1 > OHEM_THRESH;
        bool h2 = ce2 > OHEM_THRESH, h3 = ce3 > OHEM_THRESH;

        // rare path: ce <= THRESH -> global histogram (expected ~handful of hits)
        if (!(h0 && h1 && h2 && h3)) {
            float ces[4] = {ce0, ce1, ce2, ce3};
            bool  hs[4]  = {h0, h1, h2, h3};
            #pragma unroll
            for (int k = 0; k < 4; k++) {
                if (!hs[k]) {
                    int bin = min(max((int)(ces[k] * BIN_SCALE), 0), NBINS - 1);
                    atomicAdd(&g_hist_cnt[bin], 1u);
                    atomicAdd(&g_hist_sum[bin], (double)ces[k]);
                }
            }
        }

        float    fs = (h0 ? ce0 : 0.0f) + (h1 ? ce1 : 0.0f)
                    + (h2 ? ce2 : 0.0f) + (h3 ? ce3 : 0.0f);
        unsigned hc = (unsigned)h0 + (unsigned)h1 + (unsigned)h2 + (unsigned)h3;
        unsigned vc = (unsigned)valid0 + (unsigned)valid1
                    + (unsigned)valid2 + (unsigned)valid3;
        #pragma unroll
        for (int o = 16; o > 0; o >>= 1) {
            fs += __shfl_xor_sync(0xffffffffu, fs, o);
            hc += __shfl_xor_sync(0xffffffffu, hc, o);
            vc += __shfl_xor_sync(0xffffffffu, vc, o);
        }
        if (lane == 0) { s_f0[wid] = fs; s_u0[wid] = hc; s_u1[wid] = vc; }
        __syncthreads();
        if (tid == 0) {
            double ts = 0.0; unsigned th = 0, tv = 0;
            #pragma unroll
            for (int i = 0; i < 8; i++) { ts += (double)s_f0[i]; th += s_u0[i]; tv += s_u1[i]; }
            atomicAdd(&g_sum_hard, ts);
            atomicAdd(&g_cnt_hard, (unsigned long long)th);
            atomicAdd(&g_cnt_valid, (unsigned long long)tv);
        }
    } else if (bid < OHEM_BLOCKS + FOCAL_BLOCKS) {
        // ============ focal: 4 elems per thread via float4 ============
        int i4 = (bid - OHEM_BLOCKS) * THREADS + tid;
        float4 pv  = __ldcs((const float4*)hm_pred + i4);
        float4 tv4 = __ldcs((const float4*)hm_tgt + i4);

        float pl = 0.0f, nl = 0.0f, np = 0.0f;
        const float* pp = &pv.x;
        const float* tp = &tv4.x;
        #pragma unroll
        for (int k = 0; k < 4; k++) {
            float p = fmaxf(pp[k], F32_TINY);
            float t = tp[k];
            if (t == 1.0f) {
                float om = 1.0f - p;
                pl += lg2f(p) * LN2 * om * om;
                np += 1.0f;
            } else {
                float omt = 1.0f - t;
                float wgt = omt * omt; wgt *= wgt;
                nl += lg2f(1.0f - p + F32_TINY) * LN2 * p * p * wgt;
            }
        }
        #pragma unroll
        for (int o = 16; o > 0; o >>= 1) {
            pl += __shfl_xor_sync(0xffffffffu, pl, o);
            nl += __shfl_xor_sync(0xffffffffu, nl, o);
            np += __shfl_xor_sync(0xffffffffu, np, o);
        }
        if (lane == 0) { s_f0[wid] = pl; s_f1[wid] = nl; s_f2[wid] = np; }
        __syncthreads();
        if (tid == 0) {
            double tpd = 0, tnd = 0, tcd = 0;
            #pragma unroll
            for (int k = 0; k < 8; k++) { tpd += (double)s_f0[k]; tnd += (double)s_f1[k]; tcd += (double)s_f2[k]; }
            atomicAdd(&g_pos_loss, tpd);
            atomicAdd(&g_neg_loss, tnd);
            atomicAdd(&g_npos, tcd);
        }
    } else {
        // ============ L1 regression (512 boxes, 2 per thread) ============
        float l1 = 0.0f;
        #pragma unroll
        for (int r = 0; r < 2; r++) {
            int i = tid + r * THREADS;
            int b = i >> 6;
            int x = ct[i * 2 + 0];
            int y = ct[i * 2 + 1];
            const float* whb = wh + (size_t)b * 2 * HhWh;
            float v0 = whb[y * Wh + x];
            float v1 = whb[HhWh + y * Wh + x];
            const float* bb = bboxes + (size_t)i * 4;
            float w = bb[2] - bb[0];
            float h = bb[3] - bb[1];
            l1 += fabsf(v0 - w) + fabsf(v1 - h);
        }
        #pragma unroll
        for (int o = 16; o > 0; o >>= 1) l1 += __shfl_xor_sync(0xffffffffu, l1, o);
        if (lane == 0) s_f0[wid] = l1;
        __syncthreads();
        if (tid == 0) {
            double tot = 0.0;
            #pragma unroll
            for (int k = 0; k < 8; k++) tot += (double)s_f0[k];
            g_reg_sum = tot;
        }
    }

    // ===================== last-block election =====================
    __shared__ bool s_last;
    __syncthreads();
    if (tid == 0) {
        __threadfence();
        unsigned prev = atomicAdd(&g_done, 1u);
        s_last = (prev == (unsigned)(TOTAL_BLOCKS - 1));
    }
    __syncthreads();
    if (!s_last) return;
    __threadfence();

    __shared__ float s_out[4];
    if (tid == 0) {
        // classification (OHEM)
        unsigned long long nmin = g_cnt_valid / 16ull;
        double k, top;
        if (g_cnt_hard >= nmin) {
            k = (double)g_cnt_hard;
            top = g_sum_hard;
        } else {
            k = (double)nmin;
            top = g_sum_hard;
            double need = (double)(nmin - g_cnt_hard);
            for (int bin = NBINS - 1; bin >= 0 && need > 0.0; --bin) {
                unsigned c = g_hist_cnt[bin];
                if (!c) continue;
                if ((double)c <= need) { top += g_hist_sum[bin]; need -= (double)c; }
                else                   { top += g_hist_sum[bin] * (need / (double)c); need = 0.0; }
            }
        }
        float cls = (k > 0.0) ? (float)(top / k) : 0.0f;

        // centerness (focal)
        double npos = g_npos;
        double fl = (npos == 0.0) ? -g_neg_loss
                                  : -(g_pos_loss + g_neg_loss) / fmax(npos, 1.0);
        float centerness = (float)fl;

        // bbox
        float regression = (float)g_reg_sum * 0.7f;
        float bbox = regression / ((float)NBOX + 1e-7f) * 0.1f;
        float localization = (centerness + bbox) * 1.0f;

        s_out[0] = cls;
        s_out[1] = localization;
        s_out[2] = centerness;
        s_out[3] = bbox;
    }
    __syncthreads();

    if (tid < 4) out[tid] = s_out[tid];
    for (int bin = tid; bin < NBINS; bin += THREADS) {
        g_hist_sum[bin] = 0.0;
        g_hist_cnt[bin] = 0u;
    }
    if (tid == 0) {
        g_sum_hard = 0.0; g_cnt_hard = 0ull; g_cnt_valid = 0ull;
        g_pos_loss = 0.0; g_neg_loss = 0.0; g_npos = 0.0; g_reg_sum = 0.0;
        __threadfence();
        g_done = 0u;
    }
}

// ---------------- launch ----------------
extern "C" void kernel_launch(void* const* d_in, const int* in_sizes, int n_in,
                              void* d_out, int out_size)
{
    const float* seg     = (const float*)d_in[0];
    const int*   masks   = (const int*)  d_in[1];
    const float* hm_pred = (const float*)d_in[2];
    const float* hm_tgt  = (const float*)d_in[3];
    const float* wh      = (const float*)d_in[4];
    const float* bboxes  = (const float*)d_in[5];
    // d_in[6] = labels (unused by the reference loss)
    const int*   ct      = (const int*)  d_in[7];
    float* out = (float*)d_out;

    fused_loss_kernel<<<TOTAL_BLOCKS, THREADS>>>(
        seg, masks, hm_pred, hm_tgt, wh, bboxes, ct, out);
}